// round 6
// baseline (speedup 1.0000x reference)
#include <cuda_runtime.h>
#include <cstdint>

// ---------------------------------------------------------------------------
// GCN_8796093022507: 2-layer GCN collapsed to scalar edge aggregations.
// Dropout = JAX threefry2x32 partitionable path: bits(i) = o0^o1 of
// tf(key,(0,i)); foldlike split: key_j = tf(parent,(0,j)).
// R6: dropout bitmask pre-filter in edge1 (skip gather, not just atomic),
// __ldcs on index streams (keep p/mask L1-resident), 16 edges/thread.
// ---------------------------------------------------------------------------

#define MAXN 100352
#define KEEP_TH 0x66666800u   // bits < TH  <=>  uniform(bits) < 0.4f
#define INV_KEEP 2.5f         // 1/(1-0.6)

__device__ int      g_deg[MAXN];
__device__ float    g_dinv[MAXN];
__device__ float    g_p1[MAXN];
__device__ float    g_acc1[MAXN];
__device__ float    g_p2[MAXN];
__device__ float    g_acc2[MAXN];
__device__ unsigned g_mask[MAXN / 32 + 1];
__device__ int      g_is64;

__host__ __device__ __forceinline__ uint32_t rotl32(uint32_t v, int r) {
#ifdef __CUDA_ARCH__
    return __funnelshift_l(v, v, r);
#else
    return (v << r) | (v >> (32 - r));
#endif
}

__host__ __device__ __forceinline__ void tf2x32(uint32_t k0, uint32_t k1,
                                                uint32_t x0, uint32_t x1,
                                                uint32_t& o0, uint32_t& o1) {
    const uint32_t k2 = k0 ^ k1 ^ 0x1BD11BDAu;
    x0 += k0; x1 += k1;
#define TFR(r) { x0 += x1; x1 = rotl32(x1, r); x1 ^= x0; }
    TFR(13) TFR(15) TFR(26) TFR(6)
    x0 += k1; x1 += k2 + 1u;
    TFR(17) TFR(29) TFR(16) TFR(24)
    x0 += k2; x1 += k0 + 2u;
    TFR(13) TFR(15) TFR(26) TFR(6)
    x0 += k0; x1 += k1 + 3u;
    TFR(17) TFR(29) TFR(16) TFR(24)
    x0 += k1; x1 += k2 + 4u;
    TFR(13) TFR(15) TFR(26) TFR(6)
    o0 = x0 + k2; o1 = x1 + k0 + 5u;
#undef TFR
}

__device__ __forceinline__ uint32_t rbits32(uint32_t k0, uint32_t k1, uint32_t i) {
    uint32_t o0, o1;
    tf2x32(k0, k1, 0u, i, o0, o1);
    return o0 ^ o1;
}

// ---------------------------------------------------------------------------
// K0: zero scratch; detect index dtype (int64 <=> all odd 32-bit words zero).
__global__ void k_init(const unsigned int* __restrict__ ei32, int N, long long nwords) {
    int i = blockIdx.x * blockDim.x + threadIdx.x;
    int stride = gridDim.x * blockDim.x;
    for (int n = i; n < N; n += stride) {
        g_deg[n] = 0; g_acc1[n] = 0.f; g_acc2[n] = 0.f;
    }
    if (blockIdx.x == 0) {
        unsigned int v = 0;
        #pragma unroll
        for (int k = 0; k < 8; k++) {
            long long w = 1 + 2LL * (threadIdx.x * 8 + k);
            if (w < nwords) v |= ei32[w];
        }
        int nz = __syncthreads_or(v != 0);
        if (threadIdx.x == 0) g_is64 = nz ? 0 : 1;
    }
}

// ---------------------------------------------------------------------------
// Load 16 consecutive int32/int64 indices starting at elem offset `off`
// (must be 16-aligned within the array) with streaming hint.
__device__ __forceinline__ void load16(const void* eiv, long long off, int is64,
                                       int* out) {
    if (is64) {
        const longlong2* e = (const longlong2*)((const long long*)eiv + off);
        #pragma unroll
        for (int k = 0; k < 8; k++) {
            longlong2 d = __ldcs(e + k);
            out[2 * k] = (int)d.x; out[2 * k + 1] = (int)d.y;
        }
    } else {
        const int4* e = (const int4*)((const int*)eiv + off);
        #pragma unroll
        for (int k = 0; k < 4; k++) {
            int4 d = __ldcs(e + k);
            out[4 * k] = d.x; out[4 * k + 1] = d.y;
            out[4 * k + 2] = d.z; out[4 * k + 3] = d.w;
        }
    }
}

// ---------------------------------------------------------------------------
// K1: in-degree at dst. 16 edges/thread.
__global__ void __launch_bounds__(256) k_deg(const void* __restrict__ eiv, long long E) {
    long long base = 16LL * (blockIdx.x * (long long)blockDim.x + threadIdx.x);
    if (base >= E) return;
    int is64 = g_is64;
    if (base + 16 <= E) {
        int dsts[16];
        load16(eiv, E + base, is64, dsts);
        #pragma unroll
        for (int i = 0; i < 16; i++) atomicAdd(&g_deg[dsts[i]], 1);
    } else {
        int n = (int)(E - base);
        if (is64) {
            const long long* e = (const long long*)eiv;
            for (int i = 0; i < n; i++) atomicAdd(&g_deg[(int)e[E + base + i]], 1);
        } else {
            const int* e = (const int*)eiv;
            for (int i = 0; i < n; i++) atomicAdd(&g_deg[e[E + base + i]], 1);
        }
    }
}

// ---------------------------------------------------------------------------
// K2: dinv, dropout1(x), p1 = hd*dinv, keep-bitmask via ballot.
__global__ void k_node1(const float* __restrict__ x, int N,
                        uint32_t k0, uint32_t k1) {
    int n = blockIdx.x * blockDim.x + threadIdx.x;
    bool active = n < N;
    uint32_t bits = 0xFFFFFFFFu;   // dropped for inactive lanes
    float d = 0.f;
    if (active) {
        bits = rbits32(k0, k1, (uint32_t)n);
        int di = g_deg[n];
        d = di > 0 ? rsqrtf((float)di) : 0.f;
        g_dinv[n] = d;
    }
    bool keep = active && (bits < KEEP_TH);
    unsigned word = __ballot_sync(0xFFFFFFFFu, keep);
    if ((threadIdx.x & 31) == 0 && n < N + 31)
        g_mask[n >> 5] = word;
    if (active)
        g_p1[n] = keep ? x[n] * (INV_KEEP * d) : 0.f;
}

// ---------------------------------------------------------------------------
// K3: layer-1 edge scatter with bitmask pre-filter (skip gather for dropped
//     src). 16 edges/thread.
__global__ void __launch_bounds__(256) k_edge1(const void* __restrict__ eiv, long long E) {
    long long base = 16LL * (blockIdx.x * (long long)blockDim.x + threadIdx.x);
    if (base >= E) return;
    int is64 = g_is64;
    if (base + 16 <= E) {
        int srcs[16], dsts[16];
        load16(eiv, base, is64, srcs);
        load16(eiv, E + base, is64, dsts);
        unsigned keep = 0;
        #pragma unroll
        for (int i = 0; i < 16; i++) {
            unsigned w = g_mask[srcs[i] >> 5];
            keep |= ((w >> (srcs[i] & 31)) & 1u) << i;
        }
        #pragma unroll
        for (int i = 0; i < 16; i++) {
            if ((keep >> i) & 1u) {
                float v = __ldg(&g_p1[srcs[i]]);
                atomicAdd(&g_acc1[dsts[i]], v);
            }
        }
    } else {
        int n = (int)(E - base);
        for (int i = 0; i < n; i++) {
            int s, d;
            if (is64) {
                const long long* e = (const long long*)eiv;
                s = (int)e[base + i]; d = (int)e[E + base + i];
            } else {
                const int* e = (const int*)eiv;
                s = e[base + i]; d = e[E + base + i];
            }
            if ((g_mask[s >> 5] >> (s & 31)) & 1u)
                atomicAdd(&g_acc1[d], g_p1[s]);
        }
    }
}

// ---------------------------------------------------------------------------
// K4: layer-1 epilogue + dropout2 + layer-2 linear; threefry only for
//     relu-surviving channels.
__global__ void k_node2(const float* __restrict__ W1, const float* __restrict__ B1,
                        const float* __restrict__ W2, int N,
                        uint32_t k0, uint32_t k1) {
    __shared__ float w1[16], b1s[16], w2[16];
    if (threadIdx.x < 16) {
        w1[threadIdx.x] = W1[threadIdx.x];
        b1s[threadIdx.x] = B1[threadIdx.x];
        w2[threadIdx.x] = W2[threadIdx.x];
    }
    __syncthreads();
    int n = blockIdx.x * blockDim.x + threadIdx.x;
    if (n >= N) return;
    float dv = g_dinv[n];
    float a = g_acc1[n] * dv;

    unsigned mask = 0;
    #pragma unroll
    for (int c = 0; c < 16; c++) {
        float v = fmaf(a, w1[c], b1s[c]);
        mask |= (v > 0.f ? 1u : 0u) << c;
    }
    float s = 0.f;
    unsigned m = mask;
    unsigned base_ctr = (unsigned)n * 16u;
    while (m) {
        int c = __ffs(m) - 1;
        m &= m - 1;
        uint32_t bits = rbits32(k0, k1, base_ctr + (unsigned)c);
        if (bits < KEEP_TH) s += fmaf(a, w1[c], b1s[c]) * w2[c];
    }
    g_p2[n] = s * INV_KEEP * dv;
}

// ---------------------------------------------------------------------------
// K5: layer-2 edge scatter (skip exact zeros). 16 edges/thread.
__global__ void __launch_bounds__(256) k_edge2(const void* __restrict__ eiv, long long E) {
    long long base = 16LL * (blockIdx.x * (long long)blockDim.x + threadIdx.x);
    if (base >= E) return;
    int is64 = g_is64;
    if (base + 16 <= E) {
        int srcs[16], dsts[16];
        load16(eiv, base, is64, srcs);
        load16(eiv, E + base, is64, dsts);
        float v[16];
        #pragma unroll
        for (int i = 0; i < 16; i++) v[i] = __ldg(&g_p2[srcs[i]]);
        #pragma unroll
        for (int i = 0; i < 16; i++)
            if (v[i] != 0.f) atomicAdd(&g_acc2[dsts[i]], v[i]);
    } else {
        int n = (int)(E - base);
        for (int i = 0; i < n; i++) {
            int s, d;
            if (is64) {
                const long long* e = (const long long*)eiv;
                s = (int)e[base + i]; d = (int)e[E + base + i];
            } else {
                const int* e = (const int*)eiv;
                s = e[base + i]; d = e[E + base + i];
            }
            float v = g_p2[s];
            if (v != 0.f) atomicAdd(&g_acc2[d], v);
        }
    }
}

// ---------------------------------------------------------------------------
// K6: final output.
__global__ void k_out(float* __restrict__ out, const float* __restrict__ B2, int N) {
    int n = blockIdx.x * blockDim.x + threadIdx.x;
    if (n < N) out[n] = g_acc2[n] * g_dinv[n] + B2[0];
}

// ---------------------------------------------------------------------------
extern "C" void kernel_launch(void* const* d_in, const int* in_sizes, int n_in,
                              void* d_out, int out_size) {
    const float* x  = (const float*)d_in[0];
    const void*  ei = d_in[1];
    const float* W1 = (const float*)d_in[2];
    const float* B1 = (const float*)d_in[3];
    const float* W2 = (const float*)d_in[4];
    const float* B2 = (const float*)d_in[5];
    int N = in_sizes[0];
    long long E = (long long)in_sizes[1] / 2;
    if (N > MAXN) return;

    uint32_t k1a, k1b, k2a, k2b;
    tf2x32(0u, 42u, 0u, 0u, k1a, k1b);
    tf2x32(0u, 42u, 0u, 1u, k2a, k2b);

    long long nvec = (E + 15) / 16;
    int eb = (int)((nvec + 255) / 256);
    long long nwords = (long long)in_sizes[1];

    k_init<<<(N + 255) / 256, 256>>>((const unsigned int*)ei, N, nwords);
    k_deg<<<eb, 256>>>(ei, E);
    k_node1<<<(N + 255) / 256, 256>>>(x, N, k1a, k1b);
    k_edge1<<<eb, 256>>>(ei, E);
    k_node2<<<(N + 255) / 256, 256>>>(W1, B1, W2, N, k2a, k2b);
    k_edge2<<<eb, 256>>>(ei, E);
    k_out<<<(N + 255) / 256, 256>>>((float*)d_out, B2, N);
}

// round 7
// speedup vs baseline: 1.0783x; 1.0783x over previous
#include <cuda_runtime.h>
#include <cstdint>

// ---------------------------------------------------------------------------
// GCN_8796093022507: 2-layer GCN collapsed to scalar edge aggregations.
// Dropout = JAX threefry2x32 partitionable path: bits(i) = o0^o1 of
// tf(key,(0,i)); foldlike split: key_j = tf(parent,(0,j)).
// R7: 8 edges/thread (occupancy), mask pre-filter edge1, skip-zero edge2,
// default-cached index loads (exploit L2 persistence across passes).
// ---------------------------------------------------------------------------

#define MAXN 100352
#define KEEP_TH 0x66666800u   // bits < TH  <=>  uniform(bits) < 0.4f
#define INV_KEEP 2.5f         // 1/(1-0.6)

__device__ int      g_deg[MAXN];
__device__ float    g_dinv[MAXN];
__device__ float    g_p1[MAXN];
__device__ float    g_acc1[MAXN];
__device__ float    g_p2[MAXN];
__device__ float    g_acc2[MAXN];
__device__ unsigned g_mask[MAXN / 32 + 1];
__device__ int      g_is64;

__host__ __device__ __forceinline__ uint32_t rotl32(uint32_t v, int r) {
#ifdef __CUDA_ARCH__
    return __funnelshift_l(v, v, r);
#else
    return (v << r) | (v >> (32 - r));
#endif
}

__host__ __device__ __forceinline__ void tf2x32(uint32_t k0, uint32_t k1,
                                                uint32_t x0, uint32_t x1,
                                                uint32_t& o0, uint32_t& o1) {
    const uint32_t k2 = k0 ^ k1 ^ 0x1BD11BDAu;
    x0 += k0; x1 += k1;
#define TFR(r) { x0 += x1; x1 = rotl32(x1, r); x1 ^= x0; }
    TFR(13) TFR(15) TFR(26) TFR(6)
    x0 += k1; x1 += k2 + 1u;
    TFR(17) TFR(29) TFR(16) TFR(24)
    x0 += k2; x1 += k0 + 2u;
    TFR(13) TFR(15) TFR(26) TFR(6)
    x0 += k0; x1 += k1 + 3u;
    TFR(17) TFR(29) TFR(16) TFR(24)
    x0 += k1; x1 += k2 + 4u;
    TFR(13) TFR(15) TFR(26) TFR(6)
    o0 = x0 + k2; o1 = x1 + k0 + 5u;
#undef TFR
}

__device__ __forceinline__ uint32_t rbits32(uint32_t k0, uint32_t k1, uint32_t i) {
    uint32_t o0, o1;
    tf2x32(k0, k1, 0u, i, o0, o1);
    return o0 ^ o1;
}

// ---------------------------------------------------------------------------
// K0: zero scratch; detect index dtype (int64 <=> all odd 32-bit words zero).
__global__ void k_init(const unsigned int* __restrict__ ei32, int N, long long nwords) {
    int i = blockIdx.x * blockDim.x + threadIdx.x;
    int stride = gridDim.x * blockDim.x;
    for (int n = i; n < N; n += stride) {
        g_deg[n] = 0; g_acc1[n] = 0.f; g_acc2[n] = 0.f;
    }
    if (blockIdx.x == 0) {
        unsigned int v = 0;
        #pragma unroll
        for (int k = 0; k < 8; k++) {
            long long w = 1 + 2LL * (threadIdx.x * 8 + k);
            if (w < nwords) v |= ei32[w];
        }
        int nz = __syncthreads_or(v != 0);
        if (threadIdx.x == 0) g_is64 = nz ? 0 : 1;
    }
}

// ---------------------------------------------------------------------------
// Load 8 consecutive indices at element offset `off` (8-aligned).
__device__ __forceinline__ void load8(const void* eiv, long long off, int is64,
                                      int* out) {
    if (is64) {
        const longlong2* e = (const longlong2*)((const long long*)eiv + off);
        #pragma unroll
        for (int k = 0; k < 4; k++) {
            longlong2 d = e[k];
            out[2 * k] = (int)d.x; out[2 * k + 1] = (int)d.y;
        }
    } else {
        const int4* e = (const int4*)((const int*)eiv + off);
        int4 a = e[0], b = e[1];
        out[0] = a.x; out[1] = a.y; out[2] = a.z; out[3] = a.w;
        out[4] = b.x; out[5] = b.y; out[6] = b.z; out[7] = b.w;
    }
}

// ---------------------------------------------------------------------------
// K1: in-degree at dst. 8 edges/thread.
__global__ void __launch_bounds__(256) k_deg(const void* __restrict__ eiv, long long E) {
    long long base = 8LL * (blockIdx.x * (long long)blockDim.x + threadIdx.x);
    if (base >= E) return;
    int is64 = g_is64;
    if (base + 8 <= E) {
        int dsts[8];
        load8(eiv, E + base, is64, dsts);
        #pragma unroll
        for (int i = 0; i < 8; i++) atomicAdd(&g_deg[dsts[i]], 1);
    } else {
        int n = (int)(E - base);
        if (is64) {
            const long long* e = (const long long*)eiv;
            for (int i = 0; i < n; i++) atomicAdd(&g_deg[(int)e[E + base + i]], 1);
        } else {
            const int* e = (const int*)eiv;
            for (int i = 0; i < n; i++) atomicAdd(&g_deg[e[E + base + i]], 1);
        }
    }
}

// ---------------------------------------------------------------------------
// K2: dinv, dropout1(x), p1 = hd*dinv, keep-bitmask via ballot.
__global__ void k_node1(const float* __restrict__ x, int N,
                        uint32_t k0, uint32_t k1) {
    int n = blockIdx.x * blockDim.x + threadIdx.x;
    bool active = n < N;
    uint32_t bits = 0xFFFFFFFFu;
    float d = 0.f;
    if (active) {
        bits = rbits32(k0, k1, (uint32_t)n);
        int di = g_deg[n];
        d = di > 0 ? rsqrtf((float)di) : 0.f;
        g_dinv[n] = d;
    }
    bool keep = active && (bits < KEEP_TH);
    unsigned word = __ballot_sync(0xFFFFFFFFu, keep);
    if ((threadIdx.x & 31) == 0 && n < N + 31)
        g_mask[n >> 5] = word;
    if (active)
        g_p1[n] = keep ? x[n] * (INV_KEEP * d) : 0.f;
}

// ---------------------------------------------------------------------------
// K3: layer-1 edge scatter with bitmask pre-filter. 8 edges/thread.
__global__ void __launch_bounds__(256) k_edge1(const void* __restrict__ eiv, long long E) {
    long long base = 8LL * (blockIdx.x * (long long)blockDim.x + threadIdx.x);
    if (base >= E) return;
    int is64 = g_is64;
    if (base + 8 <= E) {
        int srcs[8], dsts[8];
        load8(eiv, base, is64, srcs);
        load8(eiv, E + base, is64, dsts);
        unsigned keep = 0;
        #pragma unroll
        for (int i = 0; i < 8; i++) {
            unsigned w = g_mask[srcs[i] >> 5];
            keep |= ((w >> (srcs[i] & 31)) & 1u) << i;
        }
        #pragma unroll
        for (int i = 0; i < 8; i++) {
            if ((keep >> i) & 1u) {
                float v = __ldg(&g_p1[srcs[i]]);
                atomicAdd(&g_acc1[dsts[i]], v);
            }
        }
    } else {
        int n = (int)(E - base);
        for (int i = 0; i < n; i++) {
            int s, d;
            if (is64) {
                const long long* e = (const long long*)eiv;
                s = (int)e[base + i]; d = (int)e[E + base + i];
            } else {
                const int* e = (const int*)eiv;
                s = e[base + i]; d = e[E + base + i];
            }
            if ((g_mask[s >> 5] >> (s & 31)) & 1u)
                atomicAdd(&g_acc1[d], g_p1[s]);
        }
    }
}

// ---------------------------------------------------------------------------
// K4: layer-1 epilogue + dropout2 + layer-2 linear; threefry only for
//     relu-surviving channels.
__global__ void k_node2(const float* __restrict__ W1, const float* __restrict__ B1,
                        const float* __restrict__ W2, int N,
                        uint32_t k0, uint32_t k1) {
    __shared__ float w1[16], b1s[16], w2[16];
    if (threadIdx.x < 16) {
        w1[threadIdx.x] = W1[threadIdx.x];
        b1s[threadIdx.x] = B1[threadIdx.x];
        w2[threadIdx.x] = W2[threadIdx.x];
    }
    __syncthreads();
    int n = blockIdx.x * blockDim.x + threadIdx.x;
    if (n >= N) return;
    float dv = g_dinv[n];
    float a = g_acc1[n] * dv;

    unsigned mask = 0;
    #pragma unroll
    for (int c = 0; c < 16; c++) {
        float v = fmaf(a, w1[c], b1s[c]);
        mask |= (v > 0.f ? 1u : 0u) << c;
    }
    float s = 0.f;
    unsigned m = mask;
    unsigned base_ctr = (unsigned)n * 16u;
    while (m) {
        int c = __ffs(m) - 1;
        m &= m - 1;
        uint32_t bits = rbits32(k0, k1, base_ctr + (unsigned)c);
        if (bits < KEEP_TH) s += fmaf(a, w1[c], b1s[c]) * w2[c];
    }
    g_p2[n] = s * INV_KEEP * dv;
}

// ---------------------------------------------------------------------------
// K5: layer-2 edge scatter (skip exact zeros). 8 edges/thread.
__global__ void __launch_bounds__(256) k_edge2(const void* __restrict__ eiv, long long E) {
    long long base = 8LL * (blockIdx.x * (long long)blockDim.x + threadIdx.x);
    if (base >= E) return;
    int is64 = g_is64;
    if (base + 8 <= E) {
        int srcs[8], dsts[8];
        load8(eiv, base, is64, srcs);
        load8(eiv, E + base, is64, dsts);
        float v[8];
        #pragma unroll
        for (int i = 0; i < 8; i++) v[i] = __ldg(&g_p2[srcs[i]]);
        #pragma unroll
        for (int i = 0; i < 8; i++)
            if (v[i] != 0.f) atomicAdd(&g_acc2[dsts[i]], v[i]);
    } else {
        int n = (int)(E - base);
        for (int i = 0; i < n; i++) {
            int s, d;
            if (is64) {
                const long long* e = (const long long*)eiv;
                s = (int)e[base + i]; d = (int)e[E + base + i];
            } else {
                const int* e = (const int*)eiv;
                s = e[base + i]; d = e[E + base + i];
            }
            float v = g_p2[s];
            if (v != 0.f) atomicAdd(&g_acc2[d], v);
        }
    }
}

// ---------------------------------------------------------------------------
// K6: final output.
__global__ void k_out(float* __restrict__ out, const float* __restrict__ B2, int N) {
    int n = blockIdx.x * blockDim.x + threadIdx.x;
    if (n < N) out[n] = g_acc2[n] * g_dinv[n] + B2[0];
}

// ---------------------------------------------------------------------------
extern "C" void kernel_launch(void* const* d_in, const int* in_sizes, int n_in,
                              void* d_out, int out_size) {
    const float* x  = (const float*)d_in[0];
    const void*  ei = d_in[1];
    const float* W1 = (const float*)d_in[2];
    const float* B1 = (const float*)d_in[3];
    const float* W2 = (const float*)d_in[4];
    const float* B2 = (const float*)d_in[5];
    int N = in_sizes[0];
    long long E = (long long)in_sizes[1] / 2;
    if (N > MAXN) return;

    uint32_t k1a, k1b, k2a, k2b;
    tf2x32(0u, 42u, 0u, 0u, k1a, k1b);
    tf2x32(0u, 42u, 0u, 1u, k2a, k2b);

    long long nvec = (E + 7) / 8;
    int eb = (int)((nvec + 255) / 256);
    long long nwords = (long long)in_sizes[1];

    k_init<<<(N + 255) / 256, 256>>>((const unsigned int*)ei, N, nwords);
    k_deg<<<eb, 256>>>(ei, E);
    k_node1<<<(N + 255) / 256, 256>>>(x, N, k1a, k1b);
    k_edge1<<<eb, 256>>>(ei, E);
    k_node2<<<(N + 255) / 256, 256>>>(W1, B1, W2, N, k2a, k2b);
    k_edge2<<<eb, 256>>>(ei, E);
    k_out<<<(N + 255) / 256, 256>>>((float*)d_out, B2, N);
}

// round 8
// speedup vs baseline: 1.0954x; 1.0159x over previous
#include <cuda_runtime.h>
#include <cstdint>

// ---------------------------------------------------------------------------
// GCN_8796093022507: 2-layer GCN collapsed to scalar edge aggregations.
// Dropout = JAX threefry2x32 partitionable path: bits(i) = o0^o1 of
// tf(key,(0,i)); foldlike split: key_j = tf(parent,(0,j)).
// R8: all threefry RNG (both dropout masks) computed inside the
// memory-latency-bound k_deg kernel (hidden under RED stalls), stored as
// packed ballot words. node1/node2 become mask readers (no RNG).
// ---------------------------------------------------------------------------

#define MAXN 100352
#define KEEP_TH 0x66666800u   // bits < TH  <=>  uniform(bits) < 0.4f
#define INV_KEEP 2.5f         // 1/(1-0.6)

__device__ int      g_deg[MAXN];
__device__ float    g_dinv[MAXN];
__device__ float    g_p1[MAXN];
__device__ float    g_acc1[MAXN];
__device__ float    g_p2[MAXN];
__device__ float    g_acc2[MAXN];
__device__ unsigned g_mask1[MAXN / 32 + 2];     // dropout1 keep bits, node n -> bit n
__device__ unsigned g_mask2[MAXN / 2 + 2];      // dropout2 keep bits, element 16n+c
__device__ int      g_is64;

__host__ __device__ __forceinline__ uint32_t rotl32(uint32_t v, int r) {
#ifdef __CUDA_ARCH__
    return __funnelshift_l(v, v, r);
#else
    return (v << r) | (v >> (32 - r));
#endif
}

__host__ __device__ __forceinline__ void tf2x32(uint32_t k0, uint32_t k1,
                                                uint32_t x0, uint32_t x1,
                                                uint32_t& o0, uint32_t& o1) {
    const uint32_t k2 = k0 ^ k1 ^ 0x1BD11BDAu;
    x0 += k0; x1 += k1;
#define TFR(r) { x0 += x1; x1 = rotl32(x1, r); x1 ^= x0; }
    TFR(13) TFR(15) TFR(26) TFR(6)
    x0 += k1; x1 += k2 + 1u;
    TFR(17) TFR(29) TFR(16) TFR(24)
    x0 += k2; x1 += k0 + 2u;
    TFR(13) TFR(15) TFR(26) TFR(6)
    x0 += k0; x1 += k1 + 3u;
    TFR(17) TFR(29) TFR(16) TFR(24)
    x0 += k1; x1 += k2 + 4u;
    TFR(13) TFR(15) TFR(26) TFR(6)
    o0 = x0 + k2; o1 = x1 + k0 + 5u;
#undef TFR
}

__device__ __forceinline__ uint32_t rbits32(uint32_t k0, uint32_t k1, uint32_t i) {
    uint32_t o0, o1;
    tf2x32(k0, k1, 0u, i, o0, o1);
    return o0 ^ o1;
}

// ---------------------------------------------------------------------------
// K0: zero scratch; detect index dtype (int64 <=> all odd 32-bit words zero).
__global__ void k_init(const unsigned int* __restrict__ ei32, int N, long long nwords) {
    int i = blockIdx.x * blockDim.x + threadIdx.x;
    int stride = gridDim.x * blockDim.x;
    for (int n = i; n < N; n += stride) {
        g_deg[n] = 0; g_acc1[n] = 0.f; g_acc2[n] = 0.f;
    }
    if (blockIdx.x == 0) {
        unsigned int v = 0;
        #pragma unroll
        for (int k = 0; k < 8; k++) {
            long long w = 1 + 2LL * (threadIdx.x * 8 + k);
            if (w < nwords) v |= ei32[w];
        }
        int nz = __syncthreads_or(v != 0);
        if (threadIdx.x == 0) g_is64 = nz ? 0 : 1;
    }
}

// ---------------------------------------------------------------------------
// Load 8 consecutive indices at element offset `off` (8-aligned).
__device__ __forceinline__ void load8(const void* eiv, long long off, int is64,
                                      int* out) {
    if (is64) {
        const longlong2* e = (const longlong2*)((const long long*)eiv + off);
        #pragma unroll
        for (int k = 0; k < 4; k++) {
            longlong2 d = e[k];
            out[2 * k] = (int)d.x; out[2 * k + 1] = (int)d.y;
        }
    } else {
        const int4* e = (const int4*)((const int*)eiv + off);
        int4 a = e[0], b = e[1];
        out[0] = a.x; out[1] = a.y; out[2] = a.z; out[3] = a.w;
        out[4] = b.x; out[5] = b.y; out[6] = b.z; out[7] = b.w;
    }
}

// ---------------------------------------------------------------------------
// K1: in-degree at dst (8 edges/thread) + ALL dropout RNG hidden under the
//     memory stalls. Warp-aligned ballot packing:
//     mask2: warp gw covers elements [64gw, 64gw+64): lane l does 64gw+l and
//            64gw+32+l -> two ballots = words 2gw, 2gw+1 (element e -> bit e&31).
//     mask1: lane l of warp gw does node 32gw+l -> word gw.
__global__ void __launch_bounds__(256) k_deg(const void* __restrict__ eiv, long long E,
                                             int N,
                                             uint32_t k1a, uint32_t k1b,
                                             uint32_t k2a, uint32_t k2b) {
    long long t = blockIdx.x * (long long)blockDim.x + threadIdx.x;
    int lane = threadIdx.x & 31;

    // --- RNG section (independent of memory work) ---
    {
        long long wbase = (t - lane) * 2;     // = 64 * global_warp_id
        long long TE = 16LL * N;
        long long e0 = wbase + lane, e1 = wbase + 32 + lane;
        bool kp0 = (e0 < TE) && rbits32(k2a, k2b, (uint32_t)e0) < KEEP_TH;
        bool kp1 = (e1 < TE) && rbits32(k2a, k2b, (uint32_t)e1) < KEEP_TH;
        unsigned w0 = __ballot_sync(0xFFFFFFFFu, kp0);
        unsigned w1 = __ballot_sync(0xFFFFFFFFu, kp1);
        bool kpn = (t < N) && rbits32(k1a, k1b, (uint32_t)t) < KEEP_TH;
        unsigned wn = __ballot_sync(0xFFFFFFFFu, kpn);
        if (lane == 0) {
            if (wbase < TE)      g_mask2[(int)(wbase >> 5)]     = w0;
            if (wbase + 32 < TE) g_mask2[(int)(wbase >> 5) + 1] = w1;
            if (t < N)           g_mask1[(int)(t >> 5)]         = wn;
        }
    }

    // --- degree section ---
    long long base = 8LL * t;
    if (base >= E) return;
    int is64 = g_is64;
    if (base + 8 <= E) {
        int dsts[8];
        load8(eiv, E + base, is64, dsts);
        #pragma unroll
        for (int i = 0; i < 8; i++) atomicAdd(&g_deg[dsts[i]], 1);
    } else {
        int n = (int)(E - base);
        if (is64) {
            const long long* e = (const long long*)eiv;
            for (int i = 0; i < n; i++) atomicAdd(&g_deg[(int)e[E + base + i]], 1);
        } else {
            const int* e = (const int*)eiv;
            for (int i = 0; i < n; i++) atomicAdd(&g_deg[e[E + base + i]], 1);
        }
    }
}

// ---------------------------------------------------------------------------
// K2: dinv, dropout1(x) via precomputed mask, p1 = keep * x * 2.5 * dinv.
__global__ void k_node1(const float* __restrict__ x, int N) {
    int n = blockIdx.x * blockDim.x + threadIdx.x;
    if (n >= N) return;
    int di = g_deg[n];
    float d = di > 0 ? rsqrtf((float)di) : 0.f;
    g_dinv[n] = d;
    bool keep = (g_mask1[n >> 5] >> (n & 31)) & 1u;
    g_p1[n] = keep ? x[n] * (INV_KEEP * d) : 0.f;
}

// ---------------------------------------------------------------------------
// K3: layer-1 edge scatter with bitmask pre-filter. 8 edges/thread.
__global__ void __launch_bounds__(256) k_edge1(const void* __restrict__ eiv, long long E) {
    long long base = 8LL * (blockIdx.x * (long long)blockDim.x + threadIdx.x);
    if (base >= E) return;
    int is64 = g_is64;
    if (base + 8 <= E) {
        int srcs[8], dsts[8];
        load8(eiv, base, is64, srcs);
        load8(eiv, E + base, is64, dsts);
        unsigned keep = 0;
        #pragma unroll
        for (int i = 0; i < 8; i++) {
            unsigned w = g_mask1[srcs[i] >> 5];
            keep |= ((w >> (srcs[i] & 31)) & 1u) << i;
        }
        #pragma unroll
        for (int i = 0; i < 8; i++) {
            if ((keep >> i) & 1u) {
                float v = __ldg(&g_p1[srcs[i]]);
                atomicAdd(&g_acc1[dsts[i]], v);
            }
        }
    } else {
        int n = (int)(E - base);
        for (int i = 0; i < n; i++) {
            int s, d;
            if (is64) {
                const long long* e = (const long long*)eiv;
                s = (int)e[base + i]; d = (int)e[E + base + i];
            } else {
                const int* e = (const int*)eiv;
                s = e[base + i]; d = e[E + base + i];
            }
            if ((g_mask1[s >> 5] >> (s & 31)) & 1u)
                atomicAdd(&g_acc1[d], g_p1[s]);
        }
    }
}

// ---------------------------------------------------------------------------
// K4: layer-1 epilogue + dropout2 (precomputed bits) + layer-2 linear.
//     No threefry: just iterate the kept channels (~6.4 avg), test relu.
__global__ void k_node2(const float* __restrict__ W1, const float* __restrict__ B1,
                        const float* __restrict__ W2, int N) {
    __shared__ float w1[16], b1s[16], w2[16];
    if (threadIdx.x < 16) {
        w1[threadIdx.x] = W1[threadIdx.x];
        b1s[threadIdx.x] = B1[threadIdx.x];
        w2[threadIdx.x] = W2[threadIdx.x];
    }
    __syncthreads();
    int n = blockIdx.x * blockDim.x + threadIdx.x;
    if (n >= N) return;
    float dv = g_dinv[n];
    float a = g_acc1[n] * dv;
    unsigned word = g_mask2[n >> 1];
    unsigned m = (word >> ((n & 1) * 16)) & 0xFFFFu;
    float s = 0.f;
    while (m) {
        int c = __ffs(m) - 1;
        m &= m - 1;
        float v = fmaf(a, w1[c], b1s[c]);
        if (v > 0.f) s += v * w2[c];
    }
    g_p2[n] = s * INV_KEEP * dv;
}

// ---------------------------------------------------------------------------
// K5: layer-2 edge scatter (skip exact zeros). 8 edges/thread.
__global__ void __launch_bounds__(256) k_edge2(const void* __restrict__ eiv, long long E) {
    long long base = 8LL * (blockIdx.x * (long long)blockDim.x + threadIdx.x);
    if (base >= E) return;
    int is64 = g_is64;
    if (base + 8 <= E) {
        int srcs[8], dsts[8];
        load8(eiv, base, is64, srcs);
        load8(eiv, E + base, is64, dsts);
        float v[8];
        #pragma unroll
        for (int i = 0; i < 8; i++) v[i] = __ldg(&g_p2[srcs[i]]);
        #pragma unroll
        for (int i = 0; i < 8; i++)
            if (v[i] != 0.f) atomicAdd(&g_acc2[dsts[i]], v[i]);
    } else {
        int n = (int)(E - base);
        for (int i = 0; i < n; i++) {
            int s, d;
            if (is64) {
                const long long* e = (const long long*)eiv;
                s = (int)e[base + i]; d = (int)e[E + base + i];
            } else {
                const int* e = (const int*)eiv;
                s = e[base + i]; d = e[E + base + i];
            }
            float v = g_p2[s];
            if (v != 0.f) atomicAdd(&g_acc2[d], v);
        }
    }
}

// ---------------------------------------------------------------------------
// K6: final output.
__global__ void k_out(float* __restrict__ out, const float* __restrict__ B2, int N) {
    int n = blockIdx.x * blockDim.x + threadIdx.x;
    if (n < N) out[n] = g_acc2[n] * g_dinv[n] + B2[0];
}

// ---------------------------------------------------------------------------
extern "C" void kernel_launch(void* const* d_in, const int* in_sizes, int n_in,
                              void* d_out, int out_size) {
    const float* x  = (const float*)d_in[0];
    const void*  ei = d_in[1];
    const float* W1 = (const float*)d_in[2];
    const float* B1 = (const float*)d_in[3];
    const float* W2 = (const float*)d_in[4];
    const float* B2 = (const float*)d_in[5];
    int N = in_sizes[0];
    long long E = (long long)in_sizes[1] / 2;
    if (N > MAXN) return;

    uint32_t k1a, k1b, k2a, k2b;
    tf2x32(0u, 42u, 0u, 0u, k1a, k1b);
    tf2x32(0u, 42u, 0u, 1u, k2a, k2b);

    long long nvec = (E + 7) / 8;
    int eb = (int)((nvec + 255) / 256);
    // k_deg's grid must also cover the RNG: 2 mask2-elements + 1 mask1-node
    // per thread -> need threads >= max(16N/2, N).
    long long rng_threads = (16LL * N + 1) / 2;
    int rb = (int)((rng_threads + 255) / 256);
    int db = eb > rb ? eb : rb;

    k_init<<<(N + 255) / 256, 256>>>((const unsigned int*)ei, N, (long long)in_sizes[1]);
    k_deg<<<db, 256>>>(ei, E, N, k1a, k1b, k2a, k2b);
    k_node1<<<(N + 255) / 256, 256>>>(x, N);
    k_edge1<<<eb, 256>>>(ei, E);
    k_node2<<<(N + 255) / 256, 256>>>(W1, B1, W2, N);
    k_edge2<<<eb, 256>>>(ei, E);
    k_out<<<(N + 255) / 256, 256>>>((float*)d_out, B2, N);
}